// round 9
// baseline (speedup 1.0000x reference)
#include <cuda_runtime.h>
#include <cstdint>

#define DIM 64
#define MAX_SRC 100000

// Scratch for h_src = x_src @ W_nei^T  (25.6 MB, fits in L2 alongside out)
__device__ float g_h_src[(size_t)MAX_SRC * DIM];

// Packed fp32x2 FMA (Blackwell): d = a*b + d on two lanes of a b64 reg.
#define FMA2(acc_, a_, b_) \
    asm("fma.rn.f32x2 %0, %1, %2, %0;" : "+l"(acc_) : "l"(a_), "l"(b_))

__device__ __forceinline__ uint64_t pack2(float v) {
    uint64_t r;
    asm("mov.b64 %0, {%1, %1};" : "=l"(r) : "f"(v));
    return r;
}

// Fused: blocks [0, nblk_self) compute out = x_dst@W_self^T + b_self,
// blocks [nblk_self, ...) compute h_src = x_src@W_nei^T.
// Each thread: 4 rows x 16 cols, f32x2-packed accumulators. Weight LDS is
// amortized over 4 rows (256 LDS.128/thread vs 1024 in the naive scheme).
__global__ __launch_bounds__(128) void fused_linear_kernel(
    const float* __restrict__ x_dst, const float* __restrict__ W_self,
    const float* __restrict__ b_self, float* __restrict__ out, int n_dst,
    const float* __restrict__ x_src, const float* __restrict__ W_nei,
    float* __restrict__ h_src, int n_src, int nblk_self)
{
    const float *x, *W, *bias; float* o; int n, blk;
    if ((int)blockIdx.x < nblk_self) {
        x = x_dst; W = W_self; bias = b_self; o = out; n = n_dst;
        blk = blockIdx.x;
    } else {
        x = x_src; W = W_nei; bias = nullptr; o = h_src; n = n_src;
        blk = blockIdx.x - nblk_self;
    }

    __shared__ __align__(16) float Wt[DIM * DIM];  // Wt[k*64+c] = W[c*64+k]
    __shared__ __align__(16) float bs[DIM];
    int tid = threadIdx.x;
    for (int i = tid; i < DIM * DIM; i += 128) {
        int c = i >> 6, k = i & 63;
        Wt[k * DIM + c] = W[i];
    }
    if (tid < DIM) bs[tid] = bias ? bias[tid] : 0.0f;
    __syncthreads();

    int lane = tid & 31, warp = tid >> 5;
    int sub = lane & 3;    // column group: cols [sub*16, sub*16+16)
    int rg  = lane >> 2;   // row group within warp (0..7)
    int row0 = blk * 128 + warp * 32 + rg * 4;
    int cb = sub * 16;

    // acc[r][p]: rows row0..row0+3, column pairs (cb+2p, cb+2p+1)
    uint64_t acc[4][8];
    {
        const uint64_t* bp = reinterpret_cast<const uint64_t*>(bs + cb);
        #pragma unroll
        for (int p = 0; p < 8; p++) {
            uint64_t b = bp[p];
            acc[0][p] = b; acc[1][p] = b; acc[2][p] = b; acc[3][p] = b;
        }
    }

    #pragma unroll 2
    for (int k4 = 0; k4 < 16; k4++) {
        float4 xv[4];
        #pragma unroll
        for (int r = 0; r < 4; r++) {
            int row = row0 + r;
            xv[r] = (row < n)
                  ? reinterpret_cast<const float4*>(x + (size_t)row * DIM)[k4]
                  : make_float4(0.f, 0.f, 0.f, 0.f);
        }
        #pragma unroll
        for (int j = 0; j < 4; j++) {
            int k = k4 * 4 + j;
            const ulonglong2* wp =
                reinterpret_cast<const ulonglong2*>(Wt + k * DIM + cb);
            uint64_t w[8];
            #pragma unroll
            for (int q = 0; q < 4; q++) {          // 4 x LDS.128
                ulonglong2 t = wp[q];
                w[q * 2] = t.x; w[q * 2 + 1] = t.y;
            }
            #pragma unroll
            for (int r = 0; r < 4; r++) {
                float xs = (j == 0) ? xv[r].x : (j == 1) ? xv[r].y
                         : (j == 2) ? xv[r].z : xv[r].w;
                uint64_t xx = pack2(xs);
                #pragma unroll
                for (int p = 0; p < 8; p++) FMA2(acc[r][p], xx, w[p]);
            }
        }
    }

    #pragma unroll
    for (int r = 0; r < 4; r++) {
        int row = row0 + r;
        if (row >= n) continue;
        float4* op = reinterpret_cast<float4*>(o + (size_t)row * DIM + cb);
        #pragma unroll
        for (int q = 0; q < 4; q++) {
            float a0, a1, a2, a3;
            asm("mov.b64 {%0, %1}, %2;" : "=f"(a0), "=f"(a1) : "l"(acc[r][q*2]));
            asm("mov.b64 {%0, %1}, %2;" : "=f"(a2), "=f"(a3) : "l"(acc[r][q*2+1]));
            op[q] = make_float4(a0, a1, a2, a3);
        }
    }
}

// Per edge: out[dst] += h_src[src] * w.  16 threads per edge, float4 lanes,
// vectorized fp32 reduction (red.global.add.v4.f32, sm_90+).
// Edge indices are int32 (JAX x64 disabled downcasts the int64 request).
__global__ void scatter_kernel(const int* __restrict__ sidx,
                               const int* __restrict__ didx,
                               const float* __restrict__ ew,
                               float* __restrict__ out, int E)
{
    long long t = (long long)blockIdx.x * blockDim.x + threadIdx.x;
    int edge = (int)(t >> 4);
    int sub  = (int)(t & 15);
    if (edge >= E) return;

    int s = __ldg(&sidx[edge]);
    int d = __ldg(&didx[edge]);
    float w = __ldg(&ew[edge]);

    const float4 v = *reinterpret_cast<const float4*>(
        &g_h_src[(size_t)s * DIM + sub * 4]);
    float* o = out + (size_t)d * DIM + sub * 4;
    float a = v.x * w, b = v.y * w, c = v.z * w, e = v.w * w;
    asm volatile("red.global.add.v4.f32 [%0], {%1, %2, %3, %4};"
                 :: "l"(o), "f"(a), "f"(b), "f"(c), "f"(e)
                 : "memory");
}

extern "C" void kernel_launch(void* const* d_in, const int* in_sizes, int n_in,
                              void* d_out, int out_size)
{
    const float* x_src  = (const float*)d_in[0];
    const float* x_dst  = (const float*)d_in[1];
    const int*   eidx   = (const int*)d_in[2];   // [2, E] int32
    const float* ew     = (const float*)d_in[3];
    const float* W_nei  = (const float*)d_in[4];
    const float* W_self = (const float*)d_in[5];
    const float* b_self = (const float*)d_in[6];
    float* out = (float*)d_out;

    int n_src = in_sizes[0] / DIM;
    int n_dst = in_sizes[1] / DIM;
    int E     = in_sizes[3];

    void* hsrc_ptr = nullptr;
    cudaGetSymbolAddress(&hsrc_ptr, g_h_src);

    int nblk_self = (n_dst + 127) / 128;
    int nblk_nei  = (n_src + 127) / 128;

    // 1+2) both linears in one launch (self term initializes poisoned d_out)
    fused_linear_kernel<<<nblk_self + nblk_nei, 128>>>(
        x_dst, W_self, b_self, out, n_dst,
        x_src, W_nei, (float*)hsrc_ptr, n_src, nblk_self);

    // 3) edge scatter with vectorized atomics
    long long threads = (long long)E * 16;
    int blocks = (int)((threads + 255) / 256);
    scatter_kernel<<<blocks, 256>>>(eidx, eidx + E, ew, out, E);
}

// round 10
// speedup vs baseline: 1.1186x; 1.1186x over previous
#include <cuda_runtime.h>
#include <cstdint>

#define DIM 64
#define MAX_SRC 100000

// Scratch for h_src = x_src @ W_nei^T  (25.6 MB, fits in L2 alongside out)
__device__ float g_h_src[(size_t)MAX_SRC * DIM];

// Packed fp32x2 FMA (Blackwell): d = a*b + d on two fp32 lanes of a b64 reg.
#define FMA2(acc_, a_, b_) \
    asm("fma.rn.f32x2 %0, %1, %2, %0;" : "+l"(acc_) : "l"(a_), "l"(b_))

__device__ __forceinline__ uint64_t pack2(float v) {
    uint64_t r;
    asm("mov.b64 %0, {%1, %1};" : "=l"(r) : "f"(v));
    return r;
}

// Fused: blocks [0, nblk_self) -> out = x_dst@W_self^T + b_self,
// blocks [nblk_self, ...)      -> h_src = x_src@W_nei^T.
// One row per thread; weights broadcast from smem (LDS broadcast = conflict-
// free, ~1 wavefront); f32x2-packed accumulators halve FFMA issue count.
__global__ __launch_bounds__(256) void fused_linear_kernel(
    const float* __restrict__ x_dst, const float* __restrict__ W_self,
    const float* __restrict__ b_self, float* __restrict__ out, int n_dst,
    const float* __restrict__ x_src, const float* __restrict__ W_nei,
    float* __restrict__ h_src, int n_src, int nblk_self)
{
    const float *x, *W, *bias; float* o; int n, blk;
    if ((int)blockIdx.x < nblk_self) {
        x = x_dst; W = W_self; bias = b_self; o = out; n = n_dst;
        blk = blockIdx.x;
    } else {
        x = x_src; W = W_nei; bias = nullptr; o = h_src; n = n_src;
        blk = blockIdx.x - nblk_self;
    }

    __shared__ __align__(16) float Wt[DIM * DIM];  // Wt[k*64+c] = W[c*64+k]
    __shared__ __align__(16) float bs[DIM];
    int tid = threadIdx.x;
    for (int i = tid; i < DIM * DIM; i += 256) {
        int c = i >> 6, k = i & 63;
        Wt[k * DIM + c] = W[i];
    }
    if (tid < DIM) bs[tid] = bias ? bias[tid] : 0.0f;
    __syncthreads();

    int row = blk * 256 + tid;
    if (row >= n) return;

    const float4* xr = reinterpret_cast<const float4*>(x + (size_t)row * DIM);

    // acc[p] holds output cols (2p, 2p+1)
    uint64_t acc[DIM / 2];
    {
        const uint64_t* bp = reinterpret_cast<const uint64_t*>(bs);
        #pragma unroll
        for (int p = 0; p < DIM / 2; p++) acc[p] = bp[p];
    }

    #pragma unroll 2
    for (int k4 = 0; k4 < DIM / 4; k4++) {
        float4 xv = xr[k4];
        #pragma unroll
        for (int j = 0; j < 4; j++) {
            float xs = (j == 0) ? xv.x : (j == 1) ? xv.y
                     : (j == 2) ? xv.z : xv.w;
            uint64_t xx = pack2(xs);
            int k = k4 * 4 + j;
            const ulonglong2* wp =
                reinterpret_cast<const ulonglong2*>(Wt + k * DIM);
            #pragma unroll
            for (int q = 0; q < 16; q++) {   // 16 x LDS.128 broadcast per k
                ulonglong2 t = wp[q];
                FMA2(acc[2 * q],     xx, t.x);
                FMA2(acc[2 * q + 1], xx, t.y);
            }
        }
    }

    ulonglong2* op = reinterpret_cast<ulonglong2*>(o + (size_t)row * DIM);
    #pragma unroll
    for (int q = 0; q < 16; q++)
        op[q] = make_ulonglong2(acc[2 * q], acc[2 * q + 1]);
}

// Per edge: out[dst] += h_src[src] * w.
// 16 threads per edge-group; each thread handles UNROLL consecutive edges for
// one 16B column slice. Index triples batch-loaded as int4/float4; all gathers
// issued before any RED -> MLP ~8 per thread to hide L2 latency.
#define UNROLL 4
__global__ __launch_bounds__(256) void scatter_kernel(
    const int* __restrict__ sidx, const int* __restrict__ didx,
    const float* __restrict__ ew, float* __restrict__ out, int E)
{
    long long t = (long long)blockIdx.x * blockDim.x + threadIdx.x;
    int sub    = (int)(t & 15);
    int e0     = (int)(t >> 4) * UNROLL;
    if (e0 >= E) return;

    int s[UNROLL], d[UNROLL];
    float w[UNROLL];
    if (e0 + UNROLL <= E) {          // fast path: vector index loads
        int4   sv = *reinterpret_cast<const int4*>(sidx + e0);
        int4   dv = *reinterpret_cast<const int4*>(didx + e0);
        float4 wv = *reinterpret_cast<const float4*>(ew + e0);
        s[0] = sv.x; s[1] = sv.y; s[2] = sv.z; s[3] = sv.w;
        d[0] = dv.x; d[1] = dv.y; d[2] = dv.z; d[3] = dv.w;
        w[0] = wv.x; w[1] = wv.y; w[2] = wv.z; w[3] = wv.w;
    } else {
        #pragma unroll
        for (int i = 0; i < UNROLL; i++) {
            int e = e0 + i;
            if (e < E) { s[i] = sidx[e]; d[i] = didx[e]; w[i] = ew[e]; }
            else       { s[i] = 0; d[i] = -1; w[i] = 0.0f; }
        }
    }

    float4 v[UNROLL];
    #pragma unroll
    for (int i = 0; i < UNROLL; i++)
        v[i] = *reinterpret_cast<const float4*>(
            &g_h_src[(size_t)s[i] * DIM + sub * 4]);

    #pragma unroll
    for (int i = 0; i < UNROLL; i++) {
        if (d[i] < 0) continue;
        float* o = out + (size_t)d[i] * DIM + sub * 4;
        float a = v[i].x * w[i], b = v[i].y * w[i];
        float c = v[i].z * w[i], e = v[i].w * w[i];
        asm volatile("red.global.add.v4.f32 [%0], {%1, %2, %3, %4};"
                     :: "l"(o), "f"(a), "f"(b), "f"(c), "f"(e)
                     : "memory");
    }
}

extern "C" void kernel_launch(void* const* d_in, const int* in_sizes, int n_in,
                              void* d_out, int out_size)
{
    const float* x_src  = (const float*)d_in[0];
    const float* x_dst  = (const float*)d_in[1];
    const int*   eidx   = (const int*)d_in[2];   // [2, E] int32
    const float* ew     = (const float*)d_in[3];
    const float* W_nei  = (const float*)d_in[4];
    const float* W_self = (const float*)d_in[5];
    const float* b_self = (const float*)d_in[6];
    float* out = (float*)d_out;

    int n_src = in_sizes[0] / DIM;
    int n_dst = in_sizes[1] / DIM;
    int E     = in_sizes[3];

    void* hsrc_ptr = nullptr;
    cudaGetSymbolAddress(&hsrc_ptr, g_h_src);

    int nblk_self = (n_dst + 255) / 256;
    int nblk_nei  = (n_src + 255) / 256;

    // 1+2) both linears in one launch (self term initializes poisoned d_out)
    fused_linear_kernel<<<nblk_self + nblk_nei, 256>>>(
        x_dst, W_self, b_self, out, n_dst,
        x_src, W_nei, (float*)hsrc_ptr, n_src, nblk_self);

    // 3) edge scatter, 4 edges per thread
    long long groups  = ((long long)E + UNROLL - 1) / UNROLL;
    long long threads = groups * 16;
    int blocks = (int)((threads + 255) / 256);
    scatter_kernel<<<blocks, 256>>>(eidx, eidx + E, ew, out, E);
}